// round 2
// baseline (speedup 1.0000x reference)
#include <cuda_runtime.h>
#include <cuda_bf16.h>
#include <math.h>
#include <stdint.h>

// ---------------- problem constants ----------------
#define BB 8
#define TT 4096
#define DDIM 512
#define QQ 4
#define KCB 1024
#define NROWS (BB*TT)            // 32768
#define TOUT 2048

// d_out layout (floats), tuple order: y, quantized_out, indices, loss
#define Y_OFF    0
#define QO_OFF   (BB*TOUT*DDIM)                 //  8388608
#define IDX_OFF  (QO_OFF + BB*TT*DDIM)          // 25165824
#define LOSS_OFF (IDX_OFF + QQ*BB*TT)           // 25296896

typedef unsigned long long ull;

// ---------------- device scratch (no allocations allowed) ----------------
__device__ float  g_residual[(size_t)NROWS * DDIM];   // 64 MB
__device__ float  g_cnorm[QQ * KCB];
__device__ double g_loss;

// ---------------- helpers ----------------
__device__ __forceinline__ ull fma2(ull a, ull b, ull c) {
    ull d;
    asm("fma.rn.f32x2 %0, %1, %2, %3;" : "=l"(d) : "l"(a), "l"(b), "l"(c));
    return d;
}
__device__ __forceinline__ ull pack2(float a, float b) {
    ull r;
    asm("mov.b64 %0, {%1, %2};" : "=l"(r) : "f"(a), "f"(b));
    return r;
}
__device__ __forceinline__ float2 unpk(ull v) {
    float2 f;
    asm("mov.b64 {%0, %1}, %2;" : "=f"(f.x), "=f"(f.y) : "l"(v));
    return f;
}

#define P2 130   // smem pitch in f32x2 units (bank-conflict avoidance)

// shared inner micro-kernel: 8 d-pairs, 8x8 f32x2 accumulators
__device__ __forceinline__ void mma_chunk(const ull* __restrict__ sA,
                                          const ull* __restrict__ sB,
                                          ull acc[8][8], int ty, int tx) {
#pragma unroll
    for (int j = 0; j < 8; j++) {
        ull A[8], Bf[8];
        {
            const ulonglong2* ap = (const ulonglong2*)(sA + j * P2 + ty * 8);
            ulonglong2 a0 = ap[0], a1 = ap[1], a2 = ap[2], a3 = ap[3];
            A[0] = a0.x; A[1] = a0.y; A[2] = a1.x; A[3] = a1.y;
            A[4] = a2.x; A[5] = a2.y; A[6] = a3.x; A[7] = a3.y;
        }
#pragma unroll
        for (int i = 0; i < 8; i++) Bf[i] = sB[j * P2 + tx + 16 * i];
#pragma unroll
        for (int r = 0; r < 8; r++)
#pragma unroll
            for (int i = 0; i < 8; i++)
                acc[r][i] = fma2(A[r], Bf[i], acc[r][i]);
    }
}

// ---------------- codebook half-norms (0.5*||c||^2) ----------------
__global__ void cnorm_kernel(const float* __restrict__ codebooks) {
    int row  = blockIdx.x * 8 + (threadIdx.x >> 5);   // 4096 rows
    int lane = threadIdx.x & 31;
    const float4* c4 = (const float4*)(codebooks + (size_t)row * DDIM);
    float s = 0.0f;
#pragma unroll
    for (int i = 0; i < 4; i++) {
        float4 f = c4[lane + 32 * i];
        s += f.x * f.x + f.y * f.y + f.z * f.z + f.w * f.w;
    }
#pragma unroll
    for (int off = 16; off > 0; off >>= 1) s += __shfl_xor_sync(0xffffffffu, s, off);
    if (lane == 0) g_cnorm[row] = 0.5f * s;
}

__global__ void init_kernel() { g_loss = 0.0; }

__global__ void fin_kernel(float* __restrict__ out) {
    out[0] = (float)(0.25 * g_loss * (1.0 / (double)(NROWS * (size_t)DDIM)));
}

// ---------------- VQ stage: GEMM + argmin + residual update ----------------
// grid 256 blocks (128 rows each), 256 threads.
__global__ void __launch_bounds__(256) vq_stage_kernel(
    const float* __restrict__ x,
    const float* __restrict__ codebooks,
    float* __restrict__ qsum,
    float* __restrict__ idx_out,
    int qi)
{
    __shared__ __align__(16) ull sA[8 * P2];
    __shared__ __align__(16) ull sB[8 * P2];
    __shared__ float cns[128];
    __shared__ int   best_s[128];

    const int tid  = threadIdx.x;
    const int tx   = tid & 15, ty = tid >> 4;
    const int warp = tid >> 5, lane = tid & 31;
    const int Rb   = blockIdx.x * 128;

    const float* resin = qi ? g_residual : x;
    const float* cb    = codebooks + (size_t)qi * KCB * DDIM;
    const float* aRow  = resin + (size_t)Rb * DDIM;

    float bv[8]; int bi[8];
#pragma unroll
    for (int r = 0; r < 8; r++) { bv[r] = 3.0e38f; bi[r] = 0; }

    for (int nt = 0; nt < 8; nt++) {
        const float* bRow = cb + (size_t)(nt * 128) * DDIM;

        __syncthreads();                       // protect cns from prev readers
        if (tid < 128) cns[tid] = g_cnorm[qi * KCB + nt * 128 + tid];

        ull acc[8][8];
#pragma unroll
        for (int r = 0; r < 8; r++)
#pragma unroll
            for (int i = 0; i < 8; i++) acc[r][i] = 0ull;

        // register prefetch of chunk 0
        float4 ra[2], rbv[2];
#pragma unroll
        for (int t = 0; t < 2; t++) {
            int id = tid + 256 * t;
            int m = id >> 2, q = id & 3;
            ra[t]  = *(const float4*)(aRow + (size_t)m * DDIM + q * 4);
            rbv[t] = *(const float4*)(bRow + (size_t)m * DDIM + q * 4);
        }

        for (int c = 0; c < 32; c++) {
            __syncthreads();
#pragma unroll
            for (int t = 0; t < 2; t++) {
                int id = tid + 256 * t;
                int m = id >> 2, q = id & 3;
                sA[(2 * q)     * P2 + m] = pack2(ra[t].x,  ra[t].y);
                sA[(2 * q + 1) * P2 + m] = pack2(ra[t].z,  ra[t].w);
                sB[(2 * q)     * P2 + m] = pack2(rbv[t].x, rbv[t].y);
                sB[(2 * q + 1) * P2 + m] = pack2(rbv[t].z, rbv[t].w);
            }
            __syncthreads();
            if (c < 31) {
                int d0 = (c + 1) * 16;
#pragma unroll
                for (int t = 0; t < 2; t++) {
                    int id = tid + 256 * t;
                    int m = id >> 2, q = id & 3;
                    ra[t]  = *(const float4*)(aRow + (size_t)m * DDIM + d0 + q * 4);
                    rbv[t] = *(const float4*)(bRow + (size_t)m * DDIM + d0 + q * 4);
                }
            }
            mma_chunk(sA, sB, acc, ty, tx);
        }

        // scores -> per-row running argmin (first-min tie semantics)
#pragma unroll
        for (int r = 0; r < 8; r++) {
            float lbv = 3.0e38f; int lbi = 0;
#pragma unroll
            for (int i = 0; i < 8; i++) {        // cols ascending within thread
                float2 p = unpk(acc[r][i]);
                float s = p.x + p.y;
                int col = tx + 16 * i;
                float vv = cns[col] - s;
                if (vv < lbv) { lbv = vv; lbi = nt * 128 + col; }
            }
#pragma unroll
            for (int off = 1; off < 16; off <<= 1) {
                float ov = __shfl_xor_sync(0xffffffffu, lbv, off);
                int   oi = __shfl_xor_sync(0xffffffffu, lbi, off);
                if (ov < lbv || (ov == lbv && oi < lbi)) { lbv = ov; lbi = oi; }
            }
            if (lbv < bv[r] || (lbv == bv[r] && lbi < bi[r])) { bv[r] = lbv; bi[r] = lbi; }
        }
    }

    __syncthreads();
    if (tx == 0) {
#pragma unroll
        for (int r = 0; r < 8; r++) best_s[ty * 8 + r] = bi[r];
    }
    __syncthreads();

    // fused epilogue: residual update, qsum accumulate, indices, loss
    double ls = 0.0;
    for (int rr = 0; rr < 16; rr++) {
        int row  = warp * 16 + rr;
        int gr   = Rb + row;
        int best = best_s[row];
        const float4* rp = (const float4*)(resin + (size_t)gr * DDIM);
        const float4* cp = (const float4*)(cb + (size_t)best * DDIM);
        float4* rw = (float4*)(g_residual + (size_t)gr * DDIM);
        float4* qw = (float4*)(qsum + (size_t)gr * DDIM);
        if (lane == 0) idx_out[qi * NROWS + gr] = (float)best;
#pragma unroll
        for (int it = 0; it < 4; it++) {
            int e = it * 32 + lane;
            float4 rv = rp[e], cv = cp[e];
            float4 nr = make_float4(rv.x - cv.x, rv.y - cv.y, rv.z - cv.z, rv.w - cv.w);
            ls += (double)(nr.x * nr.x + nr.y * nr.y + nr.z * nr.z + nr.w * nr.w);
            rw[e] = nr;
            if (qi == 0) {
                qw[e] = cv;
            } else {
                float4 o = qw[e];
                qw[e] = make_float4(o.x + cv.x, o.y + cv.y, o.z + cv.z, o.w + cv.w);
            }
        }
    }
#pragma unroll
    for (int off = 16; off > 0; off >>= 1) ls += __shfl_xor_sync(0xffffffffu, ls, off);
    if (lane == 0) atomicAdd(&g_loss, ls);
}

// ---------------- Conv1D (stride 2, SAME, K=5) + exact GELU ----------------
// grid (4 n-blocks, 128 m-blocks), 256 threads. A gathered from quantized_out.
__global__ void __launch_bounds__(256) conv_kernel(
    const float* __restrict__ qo,
    const float* __restrict__ w,
    float* __restrict__ y)
{
    __shared__ __align__(16) ull sA[8 * P2];
    __shared__ __align__(16) ull sB[8 * P2];

    const int tid = threadIdx.x;
    const int tx  = tid & 15, ty = tid >> 4;
    const int nb  = blockIdx.x;            // 0..3
    const int mb  = blockIdx.y;            // 0..127
    const int batch = mb >> 4;
    const int to0   = (mb & 15) * 128;
    const int n0    = nb * 128;

    const float* qb = qo + (size_t)batch * TT * DDIM;

    ull acc[8][8];
#pragma unroll
    for (int r = 0; r < 8; r++)
#pragma unroll
        for (int i = 0; i < 8; i++) acc[r][i] = 0ull;

    const int jb = tid >> 5;               // B-load: warp -> d-pair j
    const int nn = (tid & 31) * 4;

    float4 ra[2], rb0, rb1;
    // prefetch cc = 0
    {
        int k = 0, d0 = 0;
#pragma unroll
        for (int t = 0; t < 2; t++) {
            int id = tid + 256 * t;
            int m = id >> 2, q = id & 3;
            int tin = 2 * (to0 + m) - 1 + k;
            ra[t] = (tin >= 0 && tin < TT)
                  ? *(const float4*)(qb + (size_t)tin * DDIM + d0 + q * 4)
                  : make_float4(0.f, 0.f, 0.f, 0.f);
        }
        const float* wp = w + ((size_t)k * DDIM + d0 + 2 * jb) * DDIM + n0 + nn;
        rb0 = *(const float4*)wp;
        rb1 = *(const float4*)(wp + DDIM);
    }

    for (int cc = 0; cc < 160; cc++) {
        __syncthreads();
#pragma unroll
        for (int t = 0; t < 2; t++) {
            int id = tid + 256 * t;
            int m = id >> 2, q = id & 3;
            sA[(2 * q)     * P2 + m] = pack2(ra[t].x, ra[t].y);
            sA[(2 * q + 1) * P2 + m] = pack2(ra[t].z, ra[t].w);
        }
        sB[jb * P2 + nn + 0] = pack2(rb0.x, rb1.x);
        sB[jb * P2 + nn + 1] = pack2(rb0.y, rb1.y);
        sB[jb * P2 + nn + 2] = pack2(rb0.z, rb1.z);
        sB[jb * P2 + nn + 3] = pack2(rb0.w, rb1.w);
        __syncthreads();

        if (cc < 159) {
            int nc = cc + 1;
            int k = nc >> 5, d0 = (nc & 31) * 16;
#pragma unroll
            for (int t = 0; t < 2; t++) {
                int id = tid + 256 * t;
                int m = id >> 2, q = id & 3;
                int tin = 2 * (to0 + m) - 1 + k;
                ra[t] = (tin >= 0 && tin < TT)
                      ? *(const float4*)(qb + (size_t)tin * DDIM + d0 + q * 4)
                      : make_float4(0.f, 0.f, 0.f, 0.f);
            }
            const float* wp = w + ((size_t)k * DDIM + d0 + 2 * jb) * DDIM + n0 + nn;
            rb0 = *(const float4*)wp;
            rb1 = *(const float4*)(wp + DDIM);
        }
        mma_chunk(sA, sB, acc, ty, tx);
    }

    // epilogue: horizontal add + exact GELU + store
#pragma unroll
    for (int r = 0; r < 8; r++) {
        int to = to0 + ty * 8 + r;
        float* yp = y + ((size_t)batch * TOUT + to) * DDIM + n0;
#pragma unroll
        for (int i = 0; i < 8; i++) {
            float2 p = unpk(acc[r][i]);
            float s = p.x + p.y;
            float g = 0.5f * s * (1.0f + erff(s * 0.70710678118654752f));
            yp[tx + 16 * i] = g;
        }
    }
}

// ---------------- launch ----------------
extern "C" void kernel_launch(void* const* d_in, const int* in_sizes, int n_in,
                              void* d_out, int out_size) {
    (void)in_sizes; (void)n_in; (void)out_size;
    const float* x   = (const float*)d_in[0];
    const float* cbs = (const float*)d_in[1];
    const float* w   = (const float*)d_in[2];
    float* out  = (float*)d_out;
    float* y    = out + Y_OFF;
    float* qo   = out + QO_OFF;
    float* idx  = out + IDX_OFF;
    float* loss = out + LOSS_OFF;

    cnorm_kernel<<<KCB * QQ / 8, 256>>>(cbs);
    init_kernel<<<1, 1>>>();
    for (int qi = 0; qi < QQ; qi++)
        vq_stage_kernel<<<NROWS / 128, 256>>>(x, cbs, qo, idx, qi);
    fin_kernel<<<1, 1>>>(loss);
    conv_kernel<<<dim3(4, 128), 256>>>(qo, w, y);
}

// round 4
// speedup vs baseline: 1.0869x; 1.0869x over previous
#include <cuda_runtime.h>
#include <cuda_bf16.h>
#include <math.h>
#include <stdint.h>

// ---------------- problem constants ----------------
#define BB 8
#define TT 4096
#define DDIM 512
#define QQ 4
#define KCB 1024
#define NROWS (BB*TT)            // 32768
#define TOUT 2048

// d_out layout (floats), tuple order: y, quantized_out, indices, loss
#define Y_OFF    0
#define QO_OFF   (BB*TOUT*DDIM)                 //  8388608
#define IDX_OFF  (QO_OFF + BB*TT*DDIM)          // 25165824
#define LOSS_OFF (IDX_OFF + QQ*BB*TT)           // 25296896

typedef unsigned long long ull;

// ---------------- device scratch (no allocations allowed) ----------------
__device__ float  g_residual[(size_t)NROWS * DDIM];   // 64 MB
__device__ float  g_cnorm[QQ * KCB];
__device__ double g_loss;

// ---------------- helpers ----------------
__device__ __forceinline__ ull fma2(ull a, ull b, ull c) {
    ull d;
    asm("fma.rn.f32x2 %0, %1, %2, %3;" : "=l"(d) : "l"(a), "l"(b), "l"(c));
    return d;
}
__device__ __forceinline__ ull pack2(float a, float b) {
    ull r;
    asm("mov.b64 %0, {%1, %2};" : "=l"(r) : "f"(a), "f"(b));
    return r;
}
__device__ __forceinline__ float2 unpk(ull v) {
    float2 f;
    asm("mov.b64 {%0, %1}, %2;" : "=f"(f.x), "=f"(f.y) : "l"(v));
    return f;
}

#define PA 130   // A smem pitch (f32x2 units)
#define PB 66    // B smem pitch (f32x2 units)

// inner micro-kernel: 8 d-pairs, 8 rows x 4 cols f32x2 accumulators (K-paired)
__device__ __forceinline__ void mma_chunk(const ull* __restrict__ sA,
                                          const ull* __restrict__ sB,
                                          ull acc[8][4], int ty, int tx) {
#pragma unroll
    for (int j = 0; j < 8; j++) {
        ull A[8], Bf[4];
        {
            const ulonglong2* ap = (const ulonglong2*)(sA + j * PA + ty * 8);
            ulonglong2 a0 = ap[0], a1 = ap[1], a2 = ap[2], a3 = ap[3];
            A[0] = a0.x; A[1] = a0.y; A[2] = a1.x; A[3] = a1.y;
            A[4] = a2.x; A[5] = a2.y; A[6] = a3.x; A[7] = a3.y;
        }
#pragma unroll
        for (int i = 0; i < 4; i++) Bf[i] = sB[j * PB + tx + 16 * i];
#pragma unroll
        for (int r = 0; r < 8; r++)
#pragma unroll
            for (int i = 0; i < 4; i++)
                acc[r][i] = fma2(A[r], Bf[i], acc[r][i]);
    }
}

// ---------------- codebook half-norms (0.5*||c||^2) ----------------
__global__ void cnorm_kernel(const float* __restrict__ codebooks) {
    int row  = blockIdx.x * 8 + (threadIdx.x >> 5);   // 4096 rows
    int lane = threadIdx.x & 31;
    const float4* c4 = (const float4*)(codebooks + (size_t)row * DDIM);
    float s = 0.0f;
#pragma unroll
    for (int i = 0; i < 4; i++) {
        float4 f = c4[lane + 32 * i];
        s += f.x * f.x + f.y * f.y + f.z * f.z + f.w * f.w;
    }
#pragma unroll
    for (int off = 16; off > 0; off >>= 1) s += __shfl_xor_sync(0xffffffffu, s, off);
    if (lane == 0) g_cnorm[row] = 0.5f * s;
}

__global__ void init_kernel() { g_loss = 0.0; }

__global__ void fin_kernel(float* __restrict__ out) {
    out[0] = (float)(0.25 * g_loss * (1.0 / (double)((size_t)NROWS * DDIM)));
}

// ---------------- VQ stage: GEMM + argmin + residual update ----------------
// grid 256 blocks (128 rows each), 256 threads, 2 CTAs/SM.
// Tile: 128 rows x 64 cols, 16 col-tiles. Double-buffered smem, 1 bar/chunk.
__global__ void __launch_bounds__(256, 2) vq_stage_kernel(
    const float* __restrict__ x,
    const float* __restrict__ codebooks,
    float* __restrict__ qsum,
    float* __restrict__ idx_out,
    int qi)
{
    __shared__ __align__(16) ull sA[2][8 * PA];
    __shared__ __align__(16) ull sB[2][8 * PB];
    __shared__ float cns[KCB];
    __shared__ int   best_s[128];

    const int tid  = threadIdx.x;
    const int tx   = tid & 15, ty = tid >> 4;
    const int warp = tid >> 5, lane = tid & 31;
    const int Rb   = blockIdx.x * 128;

    const float* resin = qi ? g_residual : x;
    const float* cb    = codebooks + (size_t)qi * KCB * DDIM;
    const float* aRow  = resin + (size_t)Rb * DDIM;

    for (int i = tid; i < KCB; i += 256) cns[i] = g_cnorm[qi * KCB + i];

    const int m0 = tid >> 2;        // 0..63
    const int q0 = tid & 3;         // float4 slot within 16-d chunk

    float bv[8]; int bi[8];
#pragma unroll
    for (int r = 0; r < 8; r++) { bv[r] = 3.0e38f; bi[r] = 0; }

    for (int nt = 0; nt < 16; nt++) {
        const float* bRow = cb + (size_t)(nt * 64) * DDIM;

        ull acc[8][4];
#pragma unroll
        for (int r = 0; r < 8; r++)
#pragma unroll
            for (int i = 0; i < 4; i++) acc[r][i] = 0ull;

        // prologue: load + store chunk 0 into buffer 0
        {
            float4 a0 = *(const float4*)(aRow + (size_t)m0 * DDIM + q0 * 4);
            float4 a1 = *(const float4*)(aRow + (size_t)(m0 + 64) * DDIM + q0 * 4);
            float4 b  = *(const float4*)(bRow + (size_t)m0 * DDIM + q0 * 4);
            sA[0][(2 * q0)     * PA + m0]      = pack2(a0.x, a0.y);
            sA[0][(2 * q0 + 1) * PA + m0]      = pack2(a0.z, a0.w);
            sA[0][(2 * q0)     * PA + m0 + 64] = pack2(a1.x, a1.y);
            sA[0][(2 * q0 + 1) * PA + m0 + 64] = pack2(a1.z, a1.w);
            sB[0][(2 * q0)     * PB + m0]      = pack2(b.x, b.y);
            sB[0][(2 * q0 + 1) * PB + m0]      = pack2(b.z, b.w);
        }
        __syncthreads();

        for (int c = 0; c < 32; c++) {
            const int cur = c & 1;
            float4 na0 = make_float4(0.f,0.f,0.f,0.f);
            float4 na1 = na0, nb = na0;
            if (c < 31) {
                int d0 = (c + 1) * 16;
                na0 = *(const float4*)(aRow + (size_t)m0 * DDIM + d0 + q0 * 4);
                na1 = *(const float4*)(aRow + (size_t)(m0 + 64) * DDIM + d0 + q0 * 4);
                nb  = *(const float4*)(bRow + (size_t)m0 * DDIM + d0 + q0 * 4);
            }
            mma_chunk(sA[cur], sB[cur], acc, ty, tx);
            if (c < 31) {
                const int nxt = cur ^ 1;
                sA[nxt][(2 * q0)     * PA + m0]      = pack2(na0.x, na0.y);
                sA[nxt][(2 * q0 + 1) * PA + m0]      = pack2(na0.z, na0.w);
                sA[nxt][(2 * q0)     * PA + m0 + 64] = pack2(na1.x, na1.y);
                sA[nxt][(2 * q0 + 1) * PA + m0 + 64] = pack2(na1.z, na1.w);
                sB[nxt][(2 * q0)     * PB + m0]      = pack2(nb.x, nb.y);
                sB[nxt][(2 * q0 + 1) * PB + m0]      = pack2(nb.z, nb.w);
                __syncthreads();
            }
        }

        // per-tile argmin (first-min tie semantics, ascending cols)
#pragma unroll
        for (int r = 0; r < 8; r++) {
            float lbv = 3.0e38f; int lbi = 0;
#pragma unroll
            for (int i = 0; i < 4; i++) {
                float2 p = unpk(acc[r][i]);
                float s = p.x + p.y;
                int col = nt * 64 + tx + 16 * i;
                float vv = cns[col] - s;
                if (vv < lbv) { lbv = vv; lbi = col; }
            }
#pragma unroll
            for (int off = 1; off < 16; off <<= 1) {
                float ov = __shfl_xor_sync(0xffffffffu, lbv, off);
                int   oi = __shfl_xor_sync(0xffffffffu, lbi, off);
                if (ov < lbv || (ov == lbv && oi < lbi)) { lbv = ov; lbi = oi; }
            }
            if (lbv < bv[r] || (lbv == bv[r] && lbi < bi[r])) { bv[r] = lbv; bi[r] = lbi; }
        }
        __syncthreads();   // all smem readers done before next tile prologue
    }

    if (tx == 0) {
#pragma unroll
        for (int r = 0; r < 8; r++) best_s[ty * 8 + r] = bi[r];
    }
    __syncthreads();

    // fused epilogue: residual update, qsum accumulate, indices, loss
    double ls = 0.0;
    for (int rr = 0; rr < 16; rr++) {
        int row  = warp * 16 + rr;
        int gr   = Rb + row;
        int best = best_s[row];
        const float4* rp = (const float4*)(resin + (size_t)gr * DDIM);
        const float4* cp = (const float4*)(cb + (size_t)best * DDIM);
        float4* rw = (float4*)(g_residual + (size_t)gr * DDIM);
        float4* qw = (float4*)(qsum + (size_t)gr * DDIM);
        if (lane == 0) idx_out[qi * NROWS + gr] = (float)best;
#pragma unroll
        for (int it = 0; it < 4; it++) {
            int e = it * 32 + lane;
            float4 rv = rp[e], cv = cp[e];
            float4 nr = make_float4(rv.x - cv.x, rv.y - cv.y, rv.z - cv.z, rv.w - cv.w);
            ls += (double)(nr.x * nr.x + nr.y * nr.y + nr.z * nr.z + nr.w * nr.w);
            rw[e] = nr;
            if (qi == 0) {
                qw[e] = cv;
            } else {
                float4 o = qw[e];
                qw[e] = make_float4(o.x + cv.x, o.y + cv.y, o.z + cv.z, o.w + cv.w);
            }
        }
    }
#pragma unroll
    for (int off = 16; off > 0; off >>= 1) ls += __shfl_xor_sync(0xffffffffu, ls, off);
    if (lane == 0) atomicAdd(&g_loss, ls);
}

// ---------------- Conv1D (stride 2, SAME, K=5) + exact GELU ----------------
// Tile: 128 t_out x 64 n. grid (8 n-blocks, 128 m-blocks), 256 threads, 2 CTAs/SM.
__global__ void __launch_bounds__(256, 2) conv_kernel(
    const float* __restrict__ qo,
    const float* __restrict__ w,
    float* __restrict__ y)
{
    __shared__ __align__(16) ull sA[2][8 * PA];
    __shared__ __align__(16) ull sB[2][8 * PB];

    const int tid = threadIdx.x;
    const int tx  = tid & 15, ty = tid >> 4;
    const int nb  = blockIdx.x;            // 0..7
    const int mb  = blockIdx.y;            // 0..127
    const int batch = mb >> 4;
    const int to0   = (mb & 15) * 128;
    const int n0    = nb * 64;

    const float* qb = qo + (size_t)batch * TT * DDIM;

    const int m0 = tid >> 2;               // 0..63
    const int q0 = tid & 3;
    const int pB = tid >> 5;               // d-pair 0..7 for B loads
    const int c2 = (tid & 31) * 2;         // col pair base 0..62

    ull acc[8][4];
#pragma unroll
    for (int r = 0; r < 8; r++)
#pragma unroll
        for (int i = 0; i < 4; i++) acc[r][i] = 0ull;

    // prologue: chunk 0 (k=0, d0=0)
    {
        float4 a0 = make_float4(0.f,0.f,0.f,0.f), a1 = a0;
        int t0 = 2 * (to0 + m0) - 1;
        int t1 = 2 * (to0 + m0 + 64) - 1;
        if (t0 >= 0 && t0 < TT) a0 = *(const float4*)(qb + (size_t)t0 * DDIM + q0 * 4);
        if (t1 >= 0 && t1 < TT) a1 = *(const float4*)(qb + (size_t)t1 * DDIM + q0 * 4);
        const float* wp = w + (size_t)(2 * pB) * DDIM + n0 + c2;
        float2 b0 = *(const float2*)wp;
        float2 b1 = *(const float2*)(wp + DDIM);
        sA[0][(2 * q0)     * PA + m0]      = pack2(a0.x, a0.y);
        sA[0][(2 * q0 + 1) * PA + m0]      = pack2(a0.z, a0.w);
        sA[0][(2 * q0)     * PA + m0 + 64] = pack2(a1.x, a1.y);
        sA[0][(2 * q0 + 1) * PA + m0 + 64] = pack2(a1.z, a1.w);
        sB[0][pB * PB + c2]     = pack2(b0.x, b1.x);
        sB[0][pB * PB + c2 + 1] = pack2(b0.y, b1.y);
    }
    __syncthreads();

    for (int c = 0; c < 160; c++) {
        const int cur = c & 1;
        float4 na0 = make_float4(0.f,0.f,0.f,0.f), na1 = na0;
        float2 nb0 = make_float2(0.f,0.f), nb1 = nb0;
        if (c < 159) {
            int nc = c + 1;
            int k = nc >> 5, d0 = (nc & 31) * 16;
            int t0 = 2 * (to0 + m0) - 1 + k;
            int t1 = 2 * (to0 + m0 + 64) - 1 + k;
            if (t0 >= 0 && t0 < TT) na0 = *(const float4*)(qb + (size_t)t0 * DDIM + d0 + q0 * 4);
            if (t1 >= 0 && t1 < TT) na1 = *(const float4*)(qb + (size_t)t1 * DDIM + d0 + q0 * 4);
            const float* wp = w + ((size_t)k * DDIM + d0 + 2 * pB) * DDIM + n0 + c2;
            nb0 = *(const float2*)wp;
            nb1 = *(const float2*)(wp + DDIM);
        }
        mma_chunk(sA[cur], sB[cur], acc, ty, tx);
        if (c < 159) {
            const int nxt = cur ^ 1;
            sA[nxt][(2 * q0)     * PA + m0]      = pack2(na0.x, na0.y);
            sA[nxt][(2 * q0 + 1) * PA + m0]      = pack2(na0.z, na0.w);
            sA[nxt][(2 * q0)     * PA + m0 + 64] = pack2(na1.x, na1.y);
            sA[nxt][(2 * q0 + 1) * PA + m0 + 64] = pack2(na1.z, na1.w);
            sB[nxt][pB * PB + c2]     = pack2(nb0.x, nb1.x);
            sB[nxt][pB * PB + c2 + 1] = pack2(nb0.y, nb1.y);
            __syncthreads();
        }
    }

    // epilogue: horizontal add + exact GELU + store
#pragma unroll
    for (int r = 0; r < 8; r++) {
        int to = to0 + ty * 8 + r;
        float* yp = y + ((size_t)batch * TOUT + to) * DDIM + n0;
#pragma unroll
        for (int i = 0; i < 4; i++) {
            float2 p = unpk(acc[r][i]);
            float s = p.x + p.y;
            float g = 0.5f * s * (1.0f + erff(s * 0.70710678118654752f));
            yp[tx + 16 * i] = g;
        }
    }
}

// ---------------- launch ----------------
extern "C" void kernel_launch(void* const* d_in, const int* in_sizes, int n_in,
                              void* d_out, int out_size) {
    (void)in_sizes; (void)n_in; (void)out_size;
    const float* x   = (const float*)d_in[0];
    const float* cbs = (const float*)d_in[1];
    const float* w   = (const float*)d_in[2];
    float* out  = (float*)d_out;
    float* y    = out + Y_OFF;
    float* qo   = out + QO_OFF;
    float* idx  = out + IDX_OFF;
    float* loss = out + LOSS_OFF;

    cnorm_kernel<<<KCB * QQ / 8, 256>>>(cbs);
    init_kernel<<<1, 1>>>();
    for (int qi = 0; qi < QQ; qi++)
        vq_stage_kernel<<<NROWS / 128, 256>>>(x, cbs, qo, idx, qi);
    fin_kernel<<<1, 1>>>(loss);
    conv_kernel<<<dim3(8, 128), 256>>>(qo, w, y);
}